// round 1
// baseline (speedup 1.0000x reference)
#include <cuda_runtime.h>
#include <math.h>

// DelayAndSumLinear: out[b,p] = (1/norm) * sum_d apod[d] * valid[p,d] *
//                               lerp(sino[b,d,k0[p,d]], sino[b,d,k0+1], alpha[p,d])
//
// Strategy: stage sino chunks (4 dets x 2048 t x 4 batches, transposed to
// [det][t][batch]) in 128KB SMEM so the random-k0 gather becomes LDS.128
// (one float4 = all 4 batches per endpoint). LUT (64MB, the dominant HBM
// stream) is read with 32B-aligned 32B-per-pixel accesses (100% sector eff).
// Each block processes 4 chunks sequentially (accumulators in registers),
// then does 4 atomicAdds per pixel (2.1M REDG total).

#define NT      2048
#define NDET    128
#define NPIX    65536
#define NB      4
#define DCH     4                    // detectors per smem chunk
#define CPB     4                    // chunks per block (sequential)
#define GRIDY   (NDET / (DCH * CPB)) // 8 super-chunks
#define PTILES  18                   // 18*8 = 144 blocks ~= 1 wave on 148 SMs
#define THREADS 1024
#define SMEM_FLOATS (DCH * NT * NB)  // 32768 floats = 128 KB

__global__ __launch_bounds__(THREADS, 1)
void das_kernel(const float* __restrict__ lut,
                const float* __restrict__ sino,
                float* __restrict__ out)
{
    extern __shared__ float s[];   // [j][t][b] : ((j*NT + t)*NB + b)
    const int tid = threadIdx.x;

    const int tileSize = (NPIX + PTILES - 1) / PTILES;  // 3641
    const int p0 = blockIdx.x * tileSize;
    const int p1 = min(p0 + tileSize, NPIX);

    float acc[4][NB];
    #pragma unroll
    for (int i = 0; i < 4; ++i)
        #pragma unroll
        for (int b = 0; b < NB; ++b) acc[i][b] = 0.0f;

    for (int cc = 0; cc < CPB; ++cc) {
        const int c     = blockIdx.y * CPB + cc;  // 0..31
        const int dbase = c * DCH;

        __syncthreads();  // previous chunk's smem reads done
        // Fill smem, transposed: s[(j*NT + t)*NB + b] = sino[b, dbase+j, t]
        #pragma unroll
        for (int it = 0; it < SMEM_FLOATS / THREADS; ++it) {
            int idx = it * THREADS + tid;
            int b   = idx >> 13;        // / 8192
            int rem = idx & 8191;
            int j   = rem >> 11;        // / 2048
            int t   = rem & (NT - 1);
            s[(j * NT + t) * NB + b] = sino[(b * NDET + dbase + j) * NT + t];
        }
        __syncthreads();

        // Hann apodization / norm folded into per-det weight.
        float w[DCH];
        #pragma unroll
        for (int j = 0; j < DCH; ++j) {
            float d = (float)(dbase + j);
            w[j] = (0.5f - 0.5f * cosf(6.283185307179586f * d / 127.0f))
                   * (1.0f / 63.5f);   // Hann sum over 128 pts = 63.5 exactly
        }

        #pragma unroll
        for (int i = 0; i < 4; ++i) {
            int p = p0 + i * THREADS + tid;
            if (p < p1) {
                const float4* l4 =
                    (const float4*)(lut + (size_t)p * (NDET * 2) + dbase * 2);
                float4 L0 = l4[0];   // (tof0, a0, tof1, a1)
                float4 L1 = l4[1];   // (tof2, a2, tof3, a3)

                float tofs[DCH] = {L0.x, L0.z, L1.x, L1.z};
                float als [DCH] = {L0.y, L0.w, L1.y, L1.w};

                #pragma unroll
                for (int j = 0; j < DCH; ++j) {
                    float tof = tofs[j];
                    float al  = als[j];
                    float kf  = floorf(tof);
                    int   k0  = (int)fminf(fmaxf(kf, 0.0f), (float)(NT - 2));
                    float wv  = (kf >= 0.0f && kf <= (float)(NT - 2)) ? w[j] : 0.0f;

                    const float4* sp = (const float4*)s + (j * NT + k0);
                    float4 s0 = sp[0];
                    float4 s1 = sp[1];

                    float wa = wv * al;
                    float wb = wv - wa;
                    acc[i][0] = fmaf(wb, s0.x, fmaf(wa, s1.x, acc[i][0]));
                    acc[i][1] = fmaf(wb, s0.y, fmaf(wa, s1.y, acc[i][1]));
                    acc[i][2] = fmaf(wb, s0.z, fmaf(wa, s1.z, acc[i][2]));
                    acc[i][3] = fmaf(wb, s0.w, fmaf(wa, s1.w, acc[i][3]));
                }
            }
        }
    }

    #pragma unroll
    for (int i = 0; i < 4; ++i) {
        int p = p0 + i * THREADS + tid;
        if (p < p1) {
            #pragma unroll
            for (int b = 0; b < NB; ++b)
                atomicAdd(&out[b * NPIX + p], acc[i][b]);
        }
    }
}

extern "C" void kernel_launch(void* const* d_in, const int* in_sizes, int n_in,
                              void* d_out, int out_size)
{
    const float* sino = (const float*)d_in[0];  // (4,1,128,2048) = 1,048,576
    const float* lut  = (const float*)d_in[1];  // (256,256,128,2) = 16,777,216
    if (n_in >= 2 && in_sizes[0] > in_sizes[1]) {  // safety: sino is smaller
        const float* t = sino; sino = lut; lut = t;
    }
    float* out = (float*)d_out;

    // Opt in to 128KB dynamic shared memory (idempotent, capture-safe).
    cudaFuncSetAttribute(das_kernel,
                         cudaFuncAttributeMaxDynamicSharedMemorySize,
                         SMEM_FLOATS * (int)sizeof(float));

    // Output is poisoned; atomics need zeros.
    cudaMemsetAsync(d_out, 0, (size_t)out_size * sizeof(float), 0);

    dim3 grid(PTILES, GRIDY);
    das_kernel<<<grid, THREADS, SMEM_FLOATS * sizeof(float)>>>(lut, sino, out);
}

// round 3
// speedup vs baseline: 1.0878x; 1.0878x over previous
#include <cuda_runtime.h>
#include <cuda_fp16.h>
#include <math.h>

// DelayAndSumLinear, round 2.
// Changes vs R1 (which was L1/shared-bound at 74%, 47.6us):
//  - sino staged in SMEM as fp16 [det][t][4 batches] (8B per (j,t)):
//    halves gather bytes; each lerp endpoint is ONE LDS.64.
//  - conflict-free fill: 4 coalesced LDG.32 + one STS.64 per (j,t).
//  - SMEM 64KB/block -> 2 blocks/SM, occupancy ~97% (was 48%).

#define NT      2048
#define NDET    128
#define NPIX    65536
#define NB      4
#define DCH     4                    // detectors per smem chunk
#define CPB     4                    // chunks per block (sequential)
#define GRIDY   (NDET / (DCH * CPB)) // 8 super-chunks of 16 dets
#define PTILES  37                   // 37*8 = 296 blocks = 2 waves @ 2 blocks/SM
#define THREADS 1024
#define SMEM_ENTRIES (DCH * NT)      // 8192 x uint2 = 64 KB

__global__ __launch_bounds__(THREADS, 2)
void das_kernel(const float* __restrict__ lut,
                const float* __restrict__ sino,
                float* __restrict__ out)
{
    extern __shared__ uint2 s2[];   // s2[j*NT + t] = half4{b0,b1,b2,b3}
    const int tid = threadIdx.x;

    const int tileSize = (NPIX + PTILES - 1) / PTILES;  // 1772
    const int p0 = blockIdx.x * tileSize;
    const int p1 = min(p0 + tileSize, NPIX);

    float acc[2][NB];
    #pragma unroll
    for (int i = 0; i < 2; ++i)
        #pragma unroll
        for (int b = 0; b < NB; ++b) acc[i][b] = 0.0f;

    for (int cc = 0; cc < CPB; ++cc) {
        const int dbase = (blockIdx.y * CPB + cc) * DCH;

        __syncthreads();  // previous chunk's smem reads done
        // Fill: s2[j*NT + t] = half4(sino[0..3][dbase+j][t]).
        // LDG.32 coalesced per b; STS.64 at consecutive addresses (no conflicts).
        #pragma unroll
        for (int it = 0; it < SMEM_ENTRIES / THREADS; ++it) {
            int idx = it * THREADS + tid;
            int j   = idx >> 11;        // / NT
            int t   = idx & (NT - 1);
            const float* sp = sino + (size_t)(dbase + j) * NT + t;
            float f0 = sp[0 * NDET * NT];
            float f1 = sp[1 * NDET * NT];
            float f2 = sp[2 * NDET * NT];
            float f3 = sp[3 * NDET * NT];
            half2 h01 = __floats2half2_rn(f0, f1);
            half2 h23 = __floats2half2_rn(f2, f3);
            uint2 v;
            v.x = *(unsigned*)&h01;
            v.y = *(unsigned*)&h23;
            s2[idx] = v;
        }
        __syncthreads();

        // Hann apodization / norm folded into per-det weight (sum = 63.5).
        float w[DCH];
        #pragma unroll
        for (int j = 0; j < DCH; ++j) {
            float d = (float)(dbase + j);
            w[j] = (0.5f - 0.5f * cosf(6.283185307179586f * d / 127.0f))
                   * (1.0f / 63.5f);
        }

        #pragma unroll
        for (int i = 0; i < 2; ++i) {
            int p = p0 + i * THREADS + tid;
            if (p < p1) {
                const float4* l4 =
                    (const float4*)(lut + (size_t)p * (NDET * 2) + dbase * 2);
                float4 L0 = l4[0];   // (tof0, a0, tof1, a1)
                float4 L1 = l4[1];   // (tof2, a2, tof3, a3)

                float tofs[DCH] = {L0.x, L0.z, L1.x, L1.z};
                float als [DCH] = {L0.y, L0.w, L1.y, L1.w};

                #pragma unroll
                for (int j = 0; j < DCH; ++j) {
                    float tof = tofs[j];
                    float al  = als[j];
                    float kf  = floorf(tof);
                    int   k0  = (int)fminf(fmaxf(kf, 0.0f), (float)(NT - 2));
                    float wv  = (kf >= 0.0f && kf <= (float)(NT - 2)) ? w[j] : 0.0f;

                    uint2 e0 = s2[j * NT + k0];
                    uint2 e1 = s2[j * NT + k0 + 1];
                    float2 s0a = __half22float2(*(half2*)&e0.x);
                    float2 s0b = __half22float2(*(half2*)&e0.y);
                    float2 s1a = __half22float2(*(half2*)&e1.x);
                    float2 s1b = __half22float2(*(half2*)&e1.y);

                    float wa = wv * al;
                    float wb = wv - wa;
                    acc[i][0] = fmaf(wb, s0a.x, fmaf(wa, s1a.x, acc[i][0]));
                    acc[i][1] = fmaf(wb, s0a.y, fmaf(wa, s1a.y, acc[i][1]));
                    acc[i][2] = fmaf(wb, s0b.x, fmaf(wa, s1b.x, acc[i][2]));
                    acc[i][3] = fmaf(wb, s0b.y, fmaf(wa, s1b.y, acc[i][3]));
                }
            }
        }
    }

    #pragma unroll
    for (int i = 0; i < 2; ++i) {
        int p = p0 + i * THREADS + tid;
        if (p < p1) {
            #pragma unroll
            for (int b = 0; b < NB; ++b)
                atomicAdd(&out[b * NPIX + p], acc[i][b]);
        }
    }
}

extern "C" void kernel_launch(void* const* d_in, const int* in_sizes, int n_in,
                              void* d_out, int out_size)
{
    const float* sino = (const float*)d_in[0];  // (4,1,128,2048)
    const float* lut  = (const float*)d_in[1];  // (256,256,128,2)
    if (n_in >= 2 && in_sizes[0] > in_sizes[1]) {  // safety: sino is smaller
        const float* t = sino; sino = lut; lut = t;
    }
    float* out = (float*)d_out;

    cudaFuncSetAttribute(das_kernel,
                         cudaFuncAttributeMaxDynamicSharedMemorySize,
                         SMEM_ENTRIES * (int)sizeof(uint2));

    // Output is poisoned; atomics need zeros.
    cudaMemsetAsync(d_out, 0, (size_t)out_size * sizeof(float), 0);

    dim3 grid(PTILES, GRIDY);
    das_kernel<<<grid, THREADS, SMEM_ENTRIES * sizeof(uint2)>>>(lut, sino, out);
}

// round 4
// speedup vs baseline: 1.2866x; 1.1827x over previous
#include <cuda_runtime.h>
#include <cuda_fp16.h>
#include <math.h>

// DelayAndSumLinear, round 3.
// R2 was L1-wavefront-bound (66%) with issue 35%: sino-fill redundancy
// (PTILES x NDET x NT = 9.7M staged entries) and barrier-serialized phases.
// Changes:
//  - ONE 4-det chunk per block, staged once (64KB fp16 [det][t][4b]);
//    single __syncthreads in the kernel -> compute runs barrier-free.
//  - PTILES 37 -> 14 (fill entries -62%), GRIDY 8 -> 32 (448 blocks).
//  - 512 threads, launch_bounds(512,3): 3 blocks/SM, 48 warps, 42-reg budget.
//  - LUT loads streaming (__ldcs) to keep sino resident in L2.
//  - per-pixel-slot accumulators + immediate atomicAdd (8.4M spread REDG).

#define NT      2048
#define NDET    128
#define NPIX    65536
#define NB      4
#define DCH     4                    // detectors per block (single chunk)
#define GRIDY   (NDET / DCH)         // 32
#define PTILES  14                   // 14*32 = 448 blocks ~= 1 wave @3/SM
#define THREADS 512
#define SMEM_ENTRIES (DCH * NT)      // 8192 x uint2 = 64 KB

__global__ __launch_bounds__(THREADS, 3)
void das_kernel(const float* __restrict__ lut,
                const float* __restrict__ sino,
                float* __restrict__ out)
{
    extern __shared__ uint2 s2[];   // s2[j*NT + t] = half4{b0,b1,b2,b3}
    const int tid   = threadIdx.x;
    const int dbase = blockIdx.y * DCH;

    const int tileSize = (NPIX + PTILES - 1) / PTILES;  // 4682
    const int p0 = blockIdx.x * tileSize;
    const int p1 = min(p0 + tileSize, NPIX);

    // ---- stage sino chunk: 4 dets x 2048 t x 4 batches as fp16 quads ----
    #pragma unroll
    for (int it = 0; it < SMEM_ENTRIES / THREADS; ++it) {
        int idx = it * THREADS + tid;
        int j   = idx >> 11;         // / NT
        int t   = idx & (NT - 1);
        const float* sp = sino + (size_t)(dbase + j) * NT + t;
        float f0 = sp[0 * NDET * NT];
        float f1 = sp[1 * NDET * NT];
        float f2 = sp[2 * NDET * NT];
        float f3 = sp[3 * NDET * NT];
        half2 h01 = __floats2half2_rn(f0, f1);
        half2 h23 = __floats2half2_rn(f2, f3);
        uint2 v;
        v.x = *(unsigned*)&h01;
        v.y = *(unsigned*)&h23;
        s2[idx] = v;
    }

    // Hann apodization / norm folded into per-det weight (Hann sum = 63.5).
    float w[DCH];
    #pragma unroll
    for (int j = 0; j < DCH; ++j) {
        float d = (float)(dbase + j);
        w[j] = (0.5f - 0.5f * cosf(6.283185307179586f * d / 127.0f))
               * (1.0f / 63.5f);
    }

    __syncthreads();   // the only barrier: smem chunk ready

    // ---- compute: ~10 pixel slots per thread, barrier-free ----
    const int nSlots = (tileSize + THREADS - 1) / THREADS;  // 10
    for (int sl = 0; sl < nSlots; ++sl) {
        int p = p0 + sl * THREADS + tid;
        if (p >= p1) break;

        const float4* l4 =
            (const float4*)(lut + (size_t)p * (NDET * 2) + dbase * 2);
        float4 L0 = __ldcs(l4 + 0);   // (tof0, a0, tof1, a1)
        float4 L1 = __ldcs(l4 + 1);   // (tof2, a2, tof3, a3)

        float tofs[DCH] = {L0.x, L0.z, L1.x, L1.z};
        float als [DCH] = {L0.y, L0.w, L1.y, L1.w};

        float acc0 = 0.f, acc1 = 0.f, acc2 = 0.f, acc3 = 0.f;

        #pragma unroll
        for (int j = 0; j < DCH; ++j) {
            float tof = tofs[j];
            float al  = als[j];
            float kf  = floorf(tof);
            int   k0  = (int)fminf(fmaxf(kf, 0.0f), (float)(NT - 2));
            float wv  = (kf >= 0.0f && kf <= (float)(NT - 2)) ? w[j] : 0.0f;

            uint2 e0 = s2[j * NT + k0];
            uint2 e1 = s2[j * NT + k0 + 1];
            float2 s0a = __half22float2(*(half2*)&e0.x);
            float2 s0b = __half22float2(*(half2*)&e0.y);
            float2 s1a = __half22float2(*(half2*)&e1.x);
            float2 s1b = __half22float2(*(half2*)&e1.y);

            float wa = wv * al;
            float wb = wv - wa;
            acc0 = fmaf(wb, s0a.x, fmaf(wa, s1a.x, acc0));
            acc1 = fmaf(wb, s0a.y, fmaf(wa, s1a.y, acc1));
            acc2 = fmaf(wb, s0b.x, fmaf(wa, s1b.x, acc2));
            acc3 = fmaf(wb, s0b.y, fmaf(wa, s1b.y, acc3));
        }

        atomicAdd(&out[0 * NPIX + p], acc0);
        atomicAdd(&out[1 * NPIX + p], acc1);
        atomicAdd(&out[2 * NPIX + p], acc2);
        atomicAdd(&out[3 * NPIX + p], acc3);
    }
}

extern "C" void kernel_launch(void* const* d_in, const int* in_sizes, int n_in,
                              void* d_out, int out_size)
{
    const float* sino = (const float*)d_in[0];  // (4,1,128,2048)
    const float* lut  = (const float*)d_in[1];  // (256,256,128,2)
    if (n_in >= 2 && in_sizes[0] > in_sizes[1]) {  // safety: sino is smaller
        const float* t = sino; sino = lut; lut = t;
    }
    float* out = (float*)d_out;

    cudaFuncSetAttribute(das_kernel,
                         cudaFuncAttributeMaxDynamicSharedMemorySize,
                         SMEM_ENTRIES * (int)sizeof(uint2));

    // Output is poisoned; atomics need zeros.
    cudaMemsetAsync(d_out, 0, (size_t)out_size * sizeof(float), 0);

    dim3 grid(PTILES, GRIDY);
    das_kernel<<<grid, THREADS, SMEM_ENTRIES * sizeof(uint2)>>>(lut, sino, out);
}

// round 5
// speedup vs baseline: 1.3546x; 1.0529x over previous
#include <cuda_runtime.h>
#include <cuda_fp16.h>
#include <math.h>

// DelayAndSumLinear, round 4.
// R3 was L1-wavefront-bound with the LUT LDGs dominating: lane<->pixel mapping
// made every LDG.128 touch 32 distinct 128B lines (2 wf/pixel, > the gather).
// Changes:
//  - lane pairing: lane = (pixel, half). One LDG.128 per lane covers 2 dets;
//    the pixel's two lanes share one 128B line -> 1 wavefront/pixel (was 2).
//  - per-pixel partials combined with shfl_xor(1); each lane atomics 2 batches.
//  - grid 448 -> 416 blocks (13x32): fits one clean 3-blocks/SM wave (444 slots),
//    kills the 4-block straggler wave.

#define NT      2048
#define NDET    128
#define NPIX    65536
#define NB      4
#define DCH     4                    // detectors per block (single smem chunk)
#define GRIDY   (NDET / DCH)         // 32
#define PTILES  13                   // 13*32 = 416 <= 444 slots @ 3 blocks/SM
#define THREADS 512
#define SMEM_ENTRIES (DCH * NT)      // 8192 x uint2 = 64 KB

__global__ __launch_bounds__(THREADS, 3)
void das_kernel(const float* __restrict__ lut,
                const float* __restrict__ sino,
                float* __restrict__ out)
{
    extern __shared__ uint2 s2[];   // s2[j*NT + t] = half4{b0,b1,b2,b3}
    const int tid   = threadIdx.x;
    const int dbase = blockIdx.y * DCH;

    const int tileSize = (NPIX + PTILES - 1) / PTILES;  // 5042
    const int p0 = blockIdx.x * tileSize;
    const int p1 = min(p0 + tileSize, NPIX);

    // ---- stage sino chunk: 4 dets x 2048 t x 4 batches as fp16 quads ----
    #pragma unroll
    for (int it = 0; it < SMEM_ENTRIES / THREADS; ++it) {
        int idx = it * THREADS + tid;
        int j   = idx >> 11;         // / NT
        int t   = idx & (NT - 1);
        const float* sp = sino + (size_t)(dbase + j) * NT + t;
        float f0 = sp[0 * NDET * NT];
        float f1 = sp[1 * NDET * NT];
        float f2 = sp[2 * NDET * NT];
        float f3 = sp[3 * NDET * NT];
        half2 h01 = __floats2half2_rn(f0, f1);
        half2 h23 = __floats2half2_rn(f2, f3);
        uint2 v;
        v.x = *(unsigned*)&h01;
        v.y = *(unsigned*)&h23;
        s2[idx] = v;
    }

    // lane pairing: this lane owns dets {dbase+2h, dbase+2h+1} of its pixel
    const int h      = tid & 1;
    const int pl     = tid >> 1;       // pixel slot within pass (0..255)
    const int jbase  = 2 * h;          // det offset within chunk

    // Hann apodization / norm folded into per-det weight (Hann sum = 63.5).
    float w[2];
    #pragma unroll
    for (int j = 0; j < 2; ++j) {
        float d = (float)(dbase + jbase + j);
        w[j] = (0.5f - 0.5f * cosf(6.283185307179586f * d / 127.0f))
               * (1.0f / 63.5f);
    }

    __syncthreads();   // smem chunk ready

    // ---- compute: 256 pixels per pass, 2 lanes cooperate per pixel ----
    const int nPass = (tileSize + (THREADS / 2) - 1) / (THREADS / 2);
    for (int ps = 0; ps < nPass; ++ps) {
        int p = p0 + ps * (THREADS / 2) + pl;
        if (p >= p1) break;    // pixel-pair lanes exit together (same p)

        // one 16B load per lane; both lanes of a pixel hit the same 128B line
        float4 L = __ldcs((const float4*)(lut + (size_t)p * (NDET * 2)
                                              + (dbase + jbase) * 2));
        float tofs[2] = {L.x, L.z};
        float als [2] = {L.y, L.w};

        float acc0 = 0.f, acc1 = 0.f, acc2 = 0.f, acc3 = 0.f;

        #pragma unroll
        for (int j = 0; j < 2; ++j) {
            float tof = tofs[j];
            float al  = als[j];
            float kf  = floorf(tof);
            int   k0  = (int)fminf(fmaxf(kf, 0.0f), (float)(NT - 2));
            float wv  = (kf >= 0.0f && kf <= (float)(NT - 2)) ? w[j] : 0.0f;

            uint2 e0 = s2[(jbase + j) * NT + k0];
            uint2 e1 = s2[(jbase + j) * NT + k0 + 1];
            float2 s0a = __half22float2(*(half2*)&e0.x);
            float2 s0b = __half22float2(*(half2*)&e0.y);
            float2 s1a = __half22float2(*(half2*)&e1.x);
            float2 s1b = __half22float2(*(half2*)&e1.y);

            float wa = wv * al;
            float wb = wv - wa;
            acc0 = fmaf(wb, s0a.x, fmaf(wa, s1a.x, acc0));
            acc1 = fmaf(wb, s0a.y, fmaf(wa, s1a.y, acc1));
            acc2 = fmaf(wb, s0b.x, fmaf(wa, s1b.x, acc2));
            acc3 = fmaf(wb, s0b.y, fmaf(wa, s1b.y, acc3));
        }

        // combine the two half-lane partials (partner = lane^1 = same pixel)
        acc0 += __shfl_xor_sync(0xFFFFFFFFu, acc0, 1);
        acc1 += __shfl_xor_sync(0xFFFFFFFFu, acc1, 1);
        acc2 += __shfl_xor_sync(0xFFFFFFFFu, acc2, 1);
        acc3 += __shfl_xor_sync(0xFFFFFFFFu, acc3, 1);

        // lane h writes batches {2h, 2h+1}
        float outA = h ? acc2 : acc0;
        float outB = h ? acc3 : acc1;
        atomicAdd(&out[(2 * h + 0) * NPIX + p], outA);
        atomicAdd(&out[(2 * h + 1) * NPIX + p], outB);
    }
}

extern "C" void kernel_launch(void* const* d_in, const int* in_sizes, int n_in,
                              void* d_out, int out_size)
{
    const float* sino = (const float*)d_in[0];  // (4,1,128,2048)
    const float* lut  = (const float*)d_in[1];  // (256,256,128,2)
    if (n_in >= 2 && in_sizes[0] > in_sizes[1]) {  // safety: sino is smaller
        const float* t = sino; sino = lut; lut = t;
    }
    float* out = (float*)d_out;

    cudaFuncSetAttribute(das_kernel,
                         cudaFuncAttributeMaxDynamicSharedMemorySize,
                         SMEM_ENTRIES * (int)sizeof(uint2));

    // Output is poisoned; atomics need zeros.
    cudaMemsetAsync(d_out, 0, (size_t)out_size * sizeof(float), 0);

    dim3 grid(PTILES, GRIDY);
    das_kernel<<<grid, THREADS, SMEM_ENTRIES * sizeof(uint2)>>>(lut, sino, out);
}

// round 6
// speedup vs baseline: 1.4006x; 1.0339x over previous
#include <cuda_runtime.h>
#include <cuda_fp16.h>
#include <math.h>

// DelayAndSumLinear, round 5.
// R4 profile: L1 66.7%, issue 34.5%, occ 59.5% -> latency/issue-bound, not
// bandwidth-bound. Changes (wavefront counts unchanged):
//  - 2 SHFLs per pass instead of 4 (per-lane value-select exchange).
//  - software-pipelined LUT prefetch: first LDG before __syncthreads;
//    pass n+1's load issues before pass n's compute.
//  - branchless nFull-pass loop + predicated tail (no per-lane break),
//    letting ptxas overlap iterations.

#define NT      2048
#define NDET    128
#define NPIX    65536
#define NB      4
#define DCH     4                    // detectors per block (single smem chunk)
#define GRIDY   (NDET / DCH)         // 32
#define PTILES  13                   // 13*32 = 416 <= 444 slots @ 3 blocks/SM
#define THREADS 512
#define PPP     (THREADS / 2)        // pixels per pass = 256
#define SMEM_ENTRIES (DCH * NT)      // 8192 x uint2 = 64 KB

__global__ __launch_bounds__(THREADS, 3)
void das_kernel(const float* __restrict__ lut,
                const float* __restrict__ sino,
                float* __restrict__ out)
{
    extern __shared__ uint2 s2[];   // s2[j*NT + t] = half4{b0,b1,b2,b3}
    const int tid   = threadIdx.x;
    const int dbase = blockIdx.y * DCH;

    const int tileSize = (NPIX + PTILES - 1) / PTILES;  // 5042
    const int p0 = blockIdx.x * tileSize;
    const int p1 = min(p0 + tileSize, NPIX);

    // lane pairing: lane (pixel, h) owns dets {dbase+2h, dbase+2h+1}
    const int h     = tid & 1;
    const int pl    = tid >> 1;        // pixel slot within pass (0..255)
    const int jbase = 2 * h;

    // Prefetch pass 0's LUT before the fill barrier (independent of smem).
    const float* lbase = lut + (size_t)(p0 + pl) * (NDET * 2)
                             + (dbase + jbase) * 2;
    float4 L = __ldcs((const float4*)lbase);

    // ---- stage sino chunk: 4 dets x 2048 t x 4 batches as fp16 quads ----
    #pragma unroll
    for (int it = 0; it < SMEM_ENTRIES / THREADS; ++it) {
        int idx = it * THREADS + tid;
        int j   = idx >> 11;         // / NT
        int t   = idx & (NT - 1);
        const float* sp = sino + (size_t)(dbase + j) * NT + t;
        float f0 = sp[0 * NDET * NT];
        float f1 = sp[1 * NDET * NT];
        float f2 = sp[2 * NDET * NT];
        float f3 = sp[3 * NDET * NT];
        half2 h01 = __floats2half2_rn(f0, f1);
        half2 h23 = __floats2half2_rn(f2, f3);
        uint2 v;
        v.x = *(unsigned*)&h01;
        v.y = *(unsigned*)&h23;
        s2[idx] = v;
    }

    // Hann apodization / norm folded into per-det weight (Hann sum = 63.5).
    float w0, w1;
    {
        float d0 = (float)(dbase + jbase);
        w0 = (0.5f - 0.5f * cosf(6.283185307179586f * d0 / 127.0f))
             * (1.0f / 63.5f);
        w1 = (0.5f - 0.5f * cosf(6.283185307179586f * (d0 + 1.0f) / 127.0f))
             * (1.0f / 63.5f);
    }

    __syncthreads();   // smem chunk ready

    const int span  = p1 - p0;
    const int nFull = span / PPP;          // full passes (no bounds checks)
    const int tail  = span - nFull * PPP;  // leftover pixels

    // compute body for one pass; L holds (tof0,a0,tof1,a1) for this lane
    auto compute = [&](int p, const float4 Lc) {
        float acc0 = 0.f, acc1 = 0.f, acc2 = 0.f, acc3 = 0.f;
        #pragma unroll
        for (int j = 0; j < 2; ++j) {
            float tof = j ? Lc.z : Lc.x;
            float al  = j ? Lc.w : Lc.y;
            float wj  = j ? w1 : w0;
            float kf  = floorf(tof);
            int   k0  = (int)fminf(fmaxf(kf, 0.0f), (float)(NT - 2));
            float wv  = (kf >= 0.0f && kf <= (float)(NT - 2)) ? wj : 0.0f;

            uint2 e0 = s2[(jbase + j) * NT + k0];
            uint2 e1 = s2[(jbase + j) * NT + k0 + 1];
            float2 s0a = __half22float2(*(half2*)&e0.x);
            float2 s0b = __half22float2(*(half2*)&e0.y);
            float2 s1a = __half22float2(*(half2*)&e1.x);
            float2 s1b = __half22float2(*(half2*)&e1.y);

            float wa = wv * al;
            float wb = wv - wa;
            acc0 = fmaf(wb, s0a.x, fmaf(wa, s1a.x, acc0));
            acc1 = fmaf(wb, s0a.y, fmaf(wa, s1a.y, acc1));
            acc2 = fmaf(wb, s0b.x, fmaf(wa, s1b.x, acc2));
            acc3 = fmaf(wb, s0b.y, fmaf(wa, s1b.y, acc3));
        }

        // 2-shfl exchange: lane h receives exactly the partner partials it
        // writes. t1 carries acc2 (from h=0) / acc0 (from h=1), etc.
        float t1 = h ? acc0 : acc2;
        float t2 = h ? acc1 : acc3;
        float r1 = __shfl_xor_sync(0xFFFFFFFFu, t1, 1);
        float r2 = __shfl_xor_sync(0xFFFFFFFFu, t2, 1);
        float outA = (h ? acc2 : acc0) + r1;
        float outB = (h ? acc3 : acc1) + r2;
        atomicAdd(&out[(2 * h + 0) * NPIX + p], outA);
        atomicAdd(&out[(2 * h + 1) * NPIX + p], outB);
    };

    // full passes, prefetch distance 1
    for (int ps = 0; ps < nFull; ++ps) {
        float4 Lc = L;
        int pn = p0 + (ps + 1) * PPP + pl;       // next pass's pixel
        if (pn < p1)
            L = __ldcs((const float4*)(lbase + (size_t)(ps + 1) * PPP * (NDET * 2)));
        compute(p0 + ps * PPP + pl, Lc);
    }
    // tail pass (L already holds the right data if this lane participates)
    if (pl < tail)
        compute(p0 + nFull * PPP + pl, L);
}

extern "C" void kernel_launch(void* const* d_in, const int* in_sizes, int n_in,
                              void* d_out, int out_size)
{
    const float* sino = (const float*)d_in[0];  // (4,1,128,2048)
    const float* lut  = (const float*)d_in[1];  // (256,256,128,2)
    if (n_in >= 2 && in_sizes[0] > in_sizes[1]) {  // safety: sino is smaller
        const float* t = sino; sino = lut; lut = t;
    }
    float* out = (float*)d_out;

    cudaFuncSetAttribute(das_kernel,
                         cudaFuncAttributeMaxDynamicSharedMemorySize,
                         SMEM_ENTRIES * (int)sizeof(uint2));

    // Output is poisoned; atomics need zeros.
    cudaMemsetAsync(d_out, 0, (size_t)out_size * sizeof(float), 0);

    dim3 grid(PTILES, GRIDY);
    das_kernel<<<grid, THREADS, SMEM_ENTRIES * sizeof(uint2)>>>(lut, sino, out);
}